// round 7
// baseline (speedup 1.0000x reference)
#include <cuda_runtime.h>
#include <cuda_bf16.h>

#define NQ 11
#define NL 4
#define DIMS 2048
#define NF 8
#define NTHREADS 256
#define EPT (DIMS / NTHREADS)      // 8 elements per thread
#define PPT (DIMS / 2 / NTHREADS)  // 4 pairs per thread

__global__ __launch_bounds__(NTHREADS, 1)
void qsim_kernel(const float* __restrict__ X,
                 const float* __restrict__ W,
                 const float* __restrict__ Bi,
                 float* __restrict__ out) {
    __shared__ float2 gm[NL * NQ][4];   // 44 gate matrices: m00,m01,m10,m11
    __shared__ float2 sA[DIMS];
    __shared__ float2 sB[DIMS];
    __shared__ float  red[8][4];

    const int b = blockIdx.x;
    const int t = threadIdx.x;

    // ---- compute the 44 Rot gate matrices for this sample ----
    if (t < NL * NQ) {
        const int l = t / NQ, q = t % NQ;
        float ang[3];
        #pragma unroll
        for (int c = 0; c < 3; c++) {
            const int flat = l * (NQ * 3) + q * 3 + c;   // (L,Q,3) row-major
            const int f = flat & (NF - 1);               // tiled feature index
            ang[c] = X[b * NF + f] * W[flat] + Bi[flat];
        }
        const float phi = ang[0], th = ang[1], om = ang[2];
        float st, ct;
        sincosf(th * 0.5f, &st, &ct);
        const float po = (phi + om) * 0.5f;
        const float pm = (phi - om) * 0.5f;
        float spo, cpo, spm, cpm;
        sincosf(po, &spo, &cpo);
        sincosf(pm, &spm, &cpm);
        // m00 = exp(-i po) ct ; m01 = -exp(i pm) st ; m10 = exp(-i pm) st ; m11 = exp(i po) ct
        gm[t][0] = make_float2( cpo * ct, -spo * ct);
        gm[t][1] = make_float2(-cpm * st, -spm * st);
        gm[t][2] = make_float2( cpm * st, -spm * st);
        gm[t][3] = make_float2( cpo * ct,  spo * ct);
    }

    // ---- init state |0...0> ----
    #pragma unroll
    for (int e = 0; e < EPT; e++) {
        sA[t + e * NTHREADS] = make_float2(0.f, 0.f);
    }
    if (t == 0) sA[0] = make_float2(1.f, 0.f);

    // ---- precompute the CNOT-ring read permutation ----
    // ring applied in order: (0,1),(1,2),...,(9,10),(10,0); qubit q lives at bit (10-q).
    // final[j] = s[sigma_1(sigma_2(...sigma_11(j)))]  (apply last CNOT's sigma first)
    int pidx[EPT];
    #pragma unroll
    for (int e = 0; e < EPT; e++) {
        int idx = t + e * NTHREADS;
        // sigma_11: CNOT(10,0): ctrl bit 0, tgt bit 10
        idx ^= ((idx >> 0) & 1) << 10;
        #pragma unroll
        for (int c = 9; c >= 0; c--) {
            // CNOT(c, c+1): ctrl bit (10-c), tgt bit (9-c)
            idx ^= ((idx >> (10 - c)) & 1) << (9 - c);
        }
        pidx[e] = idx;
    }
    __syncthreads();

    float2* cur = sA;
    float2* nxt = sB;

    for (int l = 0; l < NL; l++) {
        // ---- 11 single-qubit gates, in place ----
        for (int q = 0; q < NQ; q++) {
            const int p = 10 - q;
            const int g = l * NQ + q;
            const float2 m00 = gm[g][0], m01 = gm[g][1];
            const float2 m10 = gm[g][2], m11 = gm[g][3];
            #pragma unroll
            for (int e = 0; e < PPT; e++) {
                const int pr = t + e * NTHREADS;
                const int i0 = ((pr >> p) << (p + 1)) | (pr & ((1 << p) - 1));
                const int i1 = i0 | (1 << p);
                const float2 a = cur[i0];
                const float2 c2 = cur[i1];
                float2 na, nb;
                na.x = m00.x * a.x - m00.y * a.y + m01.x * c2.x - m01.y * c2.y;
                na.y = m00.x * a.y + m00.y * a.x + m01.x * c2.y + m01.y * c2.x;
                nb.x = m10.x * a.x - m10.y * a.y + m11.x * c2.x - m11.y * c2.y;
                nb.y = m10.x * a.y + m10.y * a.x + m11.x * c2.y + m11.y * c2.x;
                cur[i0] = na;
                cur[i1] = nb;
            }
            __syncthreads();
        }
        // ---- CNOT ring as one fused permutation (skip on last layer: fused into measurement) ----
        if (l < NL - 1) {
            #pragma unroll
            for (int e = 0; e < EPT; e++) {
                nxt[t + e * NTHREADS] = cur[pidx[e]];
            }
            __syncthreads();
            float2* tmp = cur; cur = nxt; nxt = tmp;
        }
    }

    // ---- measurement: final[j] = cur[perm(j)], sign from j's bits ----
    float acc[4] = {0.f, 0.f, 0.f, 0.f};
    #pragma unroll
    for (int e = 0; e < EPT; e++) {
        const int j = t + e * NTHREADS;
        const float2 v = cur[pidx[e]];
        const float p2 = v.x * v.x + v.y * v.y;
        #pragma unroll
        for (int qi = 0; qi < 4; qi++) {
            const float sgn = 1.f - 2.f * (float)((j >> (10 - qi)) & 1);
            acc[qi] += sgn * p2;
        }
    }
    // warp reduce
    #pragma unroll
    for (int off = 16; off > 0; off >>= 1) {
        #pragma unroll
        for (int qi = 0; qi < 4; qi++)
            acc[qi] += __shfl_down_sync(0xffffffffu, acc[qi], off);
    }
    const int warp = t >> 5, lane = t & 31;
    if (lane == 0) {
        #pragma unroll
        for (int qi = 0; qi < 4; qi++) red[warp][qi] = acc[qi];
    }
    __syncthreads();
    if (t < 4) {
        float s = 0.f;
        #pragma unroll
        for (int w = 0; w < 8; w++) s += red[w][t];
        out[b * 4 + t] = s;
    }
}

extern "C" void kernel_launch(void* const* d_in, const int* in_sizes, int n_in,
                              void* d_out, int out_size) {
    const float* X  = (const float*)d_in[0];   // (16, 8)
    const float* W  = (const float*)d_in[1];   // (4, 11, 3)
    const float* Bi = (const float*)d_in[2];   // (4, 11, 3)
    float* out = (float*)d_out;                // (16, 4)
    qsim_kernel<<<16, NTHREADS>>>(X, W, Bi, out);
}

// round 9
// speedup vs baseline: 2.0852x; 2.0852x over previous
#include <cuda_runtime.h>
#include <cuda_bf16.h>

#define NQ 11
#define NL 4
#define DIMS 2048
#define NF 8
#define NTHREADS 256

typedef unsigned long long u64;

// ---------- packed f32x2 helpers ----------
__device__ __forceinline__ u64 pk2(float a, float b) {
    u64 r; asm("mov.b64 %0, {%1,%2};" : "=l"(r) : "f"(a), "f"(b)); return r;
}
__device__ __forceinline__ float2 upk2(u64 v) {
    float x, y; asm("mov.b64 {%0,%1}, %2;" : "=f"(x), "=f"(y) : "l"(v));
    return make_float2(x, y);
}
__device__ __forceinline__ u64 dup2(float a) { return pk2(a, a); }
__device__ __forceinline__ u64 ffma2(u64 a, u64 b, u64 c) {
    u64 d; asm("fma.rn.f32x2 %0, %1, %2, %3;" : "=l"(d) : "l"(a), "l"(b), "l"(c)); return d;
}
__device__ __forceinline__ u64 fmul2(u64 a, u64 b) {
    u64 d; asm("mul.rn.f32x2 %0, %1, %2;" : "=l"(d) : "l"(a), "l"(b)); return d;
}
__device__ __forceinline__ u64 swp2(u64 v) { float2 t = upk2(v); return pk2(t.y, t.x); }
__device__ __forceinline__ float2 cmulf(float2 a, float2 b) {
    return make_float2(a.x * b.x - a.y * b.y, a.x * b.y + a.y * b.x);
}

// elementwise packed: new = cA*A + cB*B over a packed duo (two complex in X/Y planes)
__device__ __forceinline__ void ew(u64& nX, u64& nY,
                                   u64 AX, u64 AY, u64 BX, u64 BY,
                                   u64 ax, u64 ay, u64 nay,
                                   u64 bx, u64 by, u64 nby) {
    nX = ffma2(ax, AX, ffma2(nay, AY, ffma2(bx, BX, fmul2(nby, BY))));
    nY = ffma2(ay, AX, ffma2(ax, AY, ffma2(by, BX, fmul2(bx, BY))));
}

// gate on the pack-internal bit (the two halves of each duo form the pair)
__device__ __forceinline__ void packgate(u64* X, u64* Y,
                                         float2 m00, float2 m01, float2 m10, float2 m11) {
    u64 K1 = pk2(m00.x, m11.x);
    u64 K2 = pk2(-m00.y, -m11.y);
    u64 K3 = pk2(m01.x, m10.x);
    u64 K4 = pk2(-m01.y, -m10.y);
    u64 L1 = pk2(m00.y, m11.y);
    u64 L3 = pk2(m01.y, m10.y);
    #pragma unroll
    for (int d = 0; d < 4; d++) {
        u64 Xs = swp2(X[d]), Ys = swp2(Y[d]);
        u64 nx = ffma2(K1, X[d], ffma2(K2, Y[d], ffma2(K3, Xs, fmul2(K4, Ys))));
        u64 ny = ffma2(L1, X[d], ffma2(K1, Y[d], ffma2(L3, Xs, fmul2(K3, Ys))));
        X[d] = nx; Y[d] = ny;
    }
}

// gate on duo-index bit S (pairs of duos, elementwise across the pack)
template <int S>
__device__ __forceinline__ void duogate(u64* X, u64* Y,
                                        float2 m00, float2 m01, float2 m10, float2 m11) {
    u64 a0x = dup2(m00.x), a0y = dup2(m00.y), n0y = dup2(-m00.y);
    u64 b0x = dup2(m01.x), b0y = dup2(m01.y), nb0y = dup2(-m01.y);
    u64 a1x = dup2(m11.x), a1y = dup2(m11.y), n1y = dup2(-m11.y);
    u64 b1x = dup2(m10.x), b1y = dup2(m10.y), nb1y = dup2(-m10.y);
    #pragma unroll
    for (int i = 0; i < 2; i++) {
        const int d0 = (S == 1) ? (i * 2) : i;
        const int d1 = d0 ^ S;
        u64 x0, y0, x1, y1;
        ew(x0, y0, X[d0], Y[d0], X[d1], Y[d1], a0x, a0y, n0y, b0x, b0y, nb0y);
        ew(x1, y1, X[d1], Y[d1], X[d0], Y[d0], a1x, a1y, n1y, b1x, b1y, nb1y);
        X[d0] = x0; Y[d0] = y0; X[d1] = x1; Y[d1] = y1;
    }
}

// gate on lane bit K (partner via warp shuffle)
template <int K>
__device__ __forceinline__ void lanegate(u64* X, u64* Y,
                                         float2 m00, float2 m01, float2 m10, float2 m11,
                                         int lane) {
    const bool hi = (lane >> K) & 1;
    const float2 ca = hi ? m11 : m00;
    const float2 cb = hi ? m10 : m01;
    u64 cax = dup2(ca.x), cay = dup2(ca.y), ncay = dup2(-ca.y);
    u64 cbx = dup2(cb.x), cby = dup2(cb.y), ncby = dup2(-cb.y);
    #pragma unroll
    for (int d = 0; d < 4; d++) {
        u64 OX = __shfl_xor_sync(0xffffffffu, X[d], 1 << K);
        u64 OY = __shfl_xor_sync(0xffffffffu, Y[d], 1 << K);
        u64 nx, ny;
        ew(nx, ny, X[d], Y[d], OX, OY, cax, cay, ncay, cbx, cby, ncby);
        X[d] = nx; Y[d] = ny;
    }
}

// CNOT ring forward permutation (same as verified round-6 kernel)
__device__ __forceinline__ int permf(int idx) {
    idx ^= ((idx >> 0) & 1) << 10;
    #pragma unroll
    for (int c = 9; c >= 0; c--)
        idx ^= ((idx >> (10 - c)) & 1) << (9 - c);
    return idx;
}

__global__ __launch_bounds__(NTHREADS, 1)
void qsim_kernel(const float* __restrict__ Xin,
                 const float* __restrict__ W,
                 const float* __restrict__ Bi,
                 float* __restrict__ out) {
    __shared__ float2 gm[NL * NQ][4];
    __shared__ float bx0[DIMS], by0[DIMS], bx1[DIMS], by1[DIMS];
    __shared__ float red[8][4];

    const int b = blockIdx.x;
    const int t = threadIdx.x;
    const int w = t >> 5, lane = t & 31;

    // ---- 44 Rot gate matrices ----
    if (t < NL * NQ) {
        const int l = t / NQ, q = t % NQ;
        float ang[3];
        #pragma unroll
        for (int c = 0; c < 3; c++) {
            const int flat = l * (NQ * 3) + q * 3 + c;
            ang[c] = Xin[b * NF + (flat & (NF - 1))] * W[flat] + Bi[flat];
        }
        const float phi = ang[0], th = ang[1], om = ang[2];
        float st, ct;
        sincosf(th * 0.5f, &st, &ct);
        float spo, cpo, spm, cpm;
        sincosf((phi + om) * 0.5f, &spo, &cpo);
        sincosf((phi - om) * 0.5f, &spm, &cpm);
        gm[t][0] = make_float2( cpo * ct, -spo * ct);
        gm[t][1] = make_float2(-cpm * st, -spm * st);
        gm[t][2] = make_float2( cpm * st, -spm * st);
        gm[t][3] = make_float2( cpo * ct,  spo * ct);
    }

    // ---- perm-gather SMEM addresses (layout A read side), per-thread constant ----
    int paddr[8];
    #pragma unroll
    for (int e = 0; e < 8; e++) {
        const int k = permf((t << 3) | e);
        paddr[e] = ((k & 7) << 8) | (k >> 3);
    }
    __syncthreads();

    // ---- layer 0 as direct product state (all 11 gates folded), written to buf1 ----
    {
        float2 c = make_float2(1.f, 0.f);
        #pragma unroll
        for (int i = 0; i < 8; i++) {
            const float2 f = ((t >> i) & 1) ? gm[7 - i][2] : gm[7 - i][0];
            c = cmulf(c, f);
        }
        #pragma unroll
        for (int d = 0; d < 4; d++) {
            float2 v = cmulf(c, (d & 1) ? gm[9][2] : gm[9][0]);
            v = cmulf(v, (d >> 1) ? gm[8][2] : gm[8][0]);
            const float2 e0 = cmulf(v, gm[10][0]);
            const float2 e1 = cmulf(v, gm[10][2]);
            bx1[((2 * d) << 8) | t] = e0.x;  bx1[((2 * d + 1) << 8) | t] = e1.x;
            by1[((2 * d) << 8) | t] = e0.y;  by1[((2 * d + 1) << 8) | t] = e1.y;
        }
    }
    __syncthreads();

    // ---- layer-0 CNOT ring: perm-gather into registers, layout A packed along bit0 ----
    u64 X[4], Y[4];
    #pragma unroll
    for (int d = 0; d < 4; d++) {
        X[d] = pk2(bx1[paddr[2 * d]], bx1[paddr[2 * d + 1]]);
        Y[d] = pk2(by1[paddr[2 * d]], by1[paddr[2 * d + 1]]);
    }

    const int rb = (w << 8) | lane;   // layout-B SMEM address base

    for (int l = 1; l < NL; l++) {
        const int gb = l * NQ;
        // ---- layout A gates: qubits 10 (pack), 9,8 (duo bits), 7..3 (lane bits) ----
        packgate(X, Y, gm[gb + 10][0], gm[gb + 10][1], gm[gb + 10][2], gm[gb + 10][3]);
        duogate<1>(X, Y, gm[gb + 9][0], gm[gb + 9][1], gm[gb + 9][2], gm[gb + 9][3]);
        duogate<2>(X, Y, gm[gb + 8][0], gm[gb + 8][1], gm[gb + 8][2], gm[gb + 8][3]);
        lanegate<0>(X, Y, gm[gb + 7][0], gm[gb + 7][1], gm[gb + 7][2], gm[gb + 7][3], lane);
        lanegate<1>(X, Y, gm[gb + 6][0], gm[gb + 6][1], gm[gb + 6][2], gm[gb + 6][3], lane);
        lanegate<2>(X, Y, gm[gb + 5][0], gm[gb + 5][1], gm[gb + 5][2], gm[gb + 5][3], lane);
        lanegate<3>(X, Y, gm[gb + 4][0], gm[gb + 4][1], gm[gb + 4][2], gm[gb + 4][3], lane);
        lanegate<4>(X, Y, gm[gb + 3][0], gm[gb + 3][1], gm[gb + 3][2], gm[gb + 3][3], lane);

        // ---- exchange 1: layout A -> layout B (reg bits <-> warp bits) via buf0 ----
        #pragma unroll
        for (int d = 0; d < 4; d++) {
            const float2 lx = upk2(X[d]), ly = upk2(Y[d]);
            bx0[((2 * d) << 8) | t] = lx.x;  bx0[((2 * d + 1) << 8) | t] = lx.y;
            by0[((2 * d) << 8) | t] = ly.x;  by0[((2 * d + 1) << 8) | t] = ly.y;
        }
        __syncthreads();
        #pragma unroll
        for (int d = 0; d < 4; d++) {
            const int a0 = rb | ((2 * d) << 5), a1 = rb | ((2 * d + 1) << 5);
            X[d] = pk2(bx0[a0], bx0[a1]);
            Y[d] = pk2(by0[a0], by0[a1]);
        }

        // ---- layout B gates: qubits 2 (pack), 1,0 (duo bits) ----
        packgate(X, Y, gm[gb + 2][0], gm[gb + 2][1], gm[gb + 2][2], gm[gb + 2][3]);
        duogate<1>(X, Y, gm[gb + 1][0], gm[gb + 1][1], gm[gb + 1][2], gm[gb + 1][3]);
        duogate<2>(X, Y, gm[gb + 0][0], gm[gb + 0][1], gm[gb + 0][2], gm[gb + 0][3]);

        // ---- exchange 2: CNOT ring perm, back to layout A (buf1). Last layer: fused into meas ----
        if (l < NL - 1) {
            #pragma unroll
            for (int d = 0; d < 4; d++) {
                const int a0 = rb | ((2 * d) << 5), a1 = rb | ((2 * d + 1) << 5);
                const float2 lx = upk2(X[d]), ly = upk2(Y[d]);
                bx1[a0] = lx.x;  bx1[a1] = lx.y;
                by1[a0] = ly.x;  by1[a1] = ly.y;
            }
            __syncthreads();
            #pragma unroll
            for (int d = 0; d < 4; d++) {
                X[d] = pk2(bx1[paddr[2 * d]], bx1[paddr[2 * d + 1]]);
                Y[d] = pk2(by1[paddr[2 * d]], by1[paddr[2 * d + 1]]);
            }
        }
    }

    // ---- measurement in layout B, final CNOT ring fused via inverse perm sign parities ----
    float acc0 = 0.f, acc1 = 0.f, acc2 = 0.f, acc3 = 0.f;
    #pragma unroll
    for (int d = 0; d < 4; d++) {
        const u64 P = ffma2(X[d], X[d], fmul2(Y[d], Y[d]));
        const float2 pv = upk2(P);
        #pragma unroll
        for (int h = 0; h < 2; h++) {
            const int k = ((2 * d + h) << 8) | (lane << 3) | w;
            const float p = h ? pv.y : pv.x;
            acc0 += (__popc(k & 0x3FF) & 1) ? -p : p;   // qubit 0: j bit10 = parity(k0..k9)
            acc1 += (__popc(k & 0x600) & 1) ? -p : p;   // qubit 1: j bit9  = k9^k10
            acc2 += (__popc(k & 0x700) & 1) ? -p : p;   // qubit 2: j bit8  = k8^k9^k10
            acc3 += (__popc(k & 0x780) & 1) ? -p : p;   // qubit 3: j bit7  = k7^..^k10
        }
    }
    #pragma unroll
    for (int off = 16; off > 0; off >>= 1) {
        acc0 += __shfl_down_sync(0xffffffffu, acc0, off);
        acc1 += __shfl_down_sync(0xffffffffu, acc1, off);
        acc2 += __shfl_down_sync(0xffffffffu, acc2, off);
        acc3 += __shfl_down_sync(0xffffffffu, acc3, off);
    }
    if (lane == 0) {
        red[w][0] = acc0; red[w][1] = acc1; red[w][2] = acc2; red[w][3] = acc3;
    }
    __syncthreads();
    if (t < 4) {
        float s = 0.f;
        #pragma unroll
        for (int ww = 0; ww < 8; ww++) s += red[ww][t];
        out[b * 4 + t] = s;
    }
}

extern "C" void kernel_launch(void* const* d_in, const int* in_sizes, int n_in,
                              void* d_out, int out_size) {
    const float* X  = (const float*)d_in[0];   // (16, 8)
    const float* W  = (const float*)d_in[1];   // (4, 11, 3)
    const float* Bi = (const float*)d_in[2];   // (4, 11, 3)
    float* out = (float*)d_out;                // (16, 4)
    qsim_kernel<<<16, NTHREADS>>>(X, W, Bi, out);
}